// round 3
// baseline (speedup 1.0000x reference)
#include <cuda_runtime.h>
#include <math.h>

#define N_SEQ   256
#define T_LEN   128
#define EMBED   512
#define UNITS   512
#define GATEC   2048          // 4*UNITS
#define M_ALL   (N_SEQ * T_LEN)   // 32768

// ---------------- scratch (static device globals; no allocation allowed) ----
__device__ float g_xW[2][M_ALL][GATEC];        // 512 MB: precomputed x@W + b, per direction
__device__ float g_h[2][2][N_SEQ][UNITS];      // [dir][parity][n][u] double-buffered hidden
__device__ float g_c[2][N_SEQ][UNITS];         // [dir][n][u] cell state

// ---------------- init: zero recurrent state every call (graph replays!) ----
__global__ void init_kernel()
{
    int i = blockIdx.x * 256 + threadIdx.x;
    float* h = &g_h[0][0][0][0];
    float* c = &g_c[0][0][0];
    if (i < 2 * 2 * N_SEQ * UNITS) h[i] = 0.0f;
    if (i < 2 * N_SEQ * UNITS)     c[i] = 0.0f;
}

// ---------------- fused embedding gather + input projection GEMM ------------
// out[dir][m][n] = emb_table[ids[m]] @ W_dir + b_dir
// CTA tile: 128 (M) x 64 (N), 256 threads, 8x4 micro-tile, K-chunk 32.
__global__ void __launch_bounds__(256, 2)
xw_kernel(const int* __restrict__ x, const float* __restrict__ emb,
          const float* __restrict__ Wf, const float* __restrict__ bf,
          const float* __restrict__ Wb, const float* __restrict__ bb)
{
    const int nt  = blockIdx.x;          // 0..31  (N tiles of 64)
    const int mt  = blockIdx.y;          // 0..255 (M tiles of 128)
    const int dir = blockIdx.z;          // 0 fwd, 1 bwd
    const float* __restrict__ W    = dir ? Wb : Wf;
    const float* __restrict__ bias = dir ? bb : bf;
    const int m0 = mt * 128;
    const int n0 = nt * 64;

    __shared__ float sa[32][132];        // A tile, transposed [k][m], pad for 16B align
    __shared__ float sb[32][64];         // B tile [k][n]
    __shared__ int   sid[128];

    const int tid = threadIdx.x;
    if (tid < 128) sid[tid] = x[m0 + tid];
    __syncthreads();

    // A-load mapping: each thread loads 16 floats (4x float4) of one emb row
    const int arow = tid & 127;
    const int aseg = (tid >> 7) * 16;
    const size_t aoff = (size_t)sid[arow] * EMBED + aseg;

    // compute mapping: 16x16 thread grid, 8 rows x 4 cols per thread
    const int rg = (tid >> 4) * 8;
    const int cg = (tid & 15) * 4;

    float acc[8][4];
#pragma unroll
    for (int r = 0; r < 8; r++)
#pragma unroll
        for (int c = 0; c < 4; c++) acc[r][c] = 0.0f;

    for (int k0 = 0; k0 < EMBED; k0 += 32) {
        // gather A (emb rows) -> transposed smem; STS conflict-free (arow spans banks)
#pragma unroll
        for (int i = 0; i < 4; i++) {
            float4 v = *(const float4*)(emb + aoff + k0 + i * 4);
            int kk = aseg + i * 4;
            sa[kk + 0][arow] = v.x;
            sa[kk + 1][arow] = v.y;
            sa[kk + 2][arow] = v.z;
            sa[kk + 3][arow] = v.w;
        }
        // load B: 32x64 floats = 512 float4, 2 per thread, contiguous in smem
#pragma unroll
        for (int j = 0; j < 2; j++) {
            int idx = tid * 2 + j;
            int kk  = idx >> 4;
            int cc  = (idx & 15) * 4;
            *(float4*)&sb[kk][cc] =
                *(const float4*)(W + (size_t)(k0 + kk) * GATEC + n0 + cc);
        }
        __syncthreads();

#pragma unroll 16
        for (int k = 0; k < 32; k++) {
            const float4 b4 = *(const float4*)&sb[k][cg];
            const float4 x0 = *(const float4*)&sa[k][rg];
            const float4 x1 = *(const float4*)&sa[k][rg + 4];
            const float av[8] = {x0.x, x0.y, x0.z, x0.w, x1.x, x1.y, x1.z, x1.w};
#pragma unroll
            for (int r = 0; r < 8; r++) {
                acc[r][0] = fmaf(av[r], b4.x, acc[r][0]);
                acc[r][1] = fmaf(av[r], b4.y, acc[r][1]);
                acc[r][2] = fmaf(av[r], b4.z, acc[r][2]);
                acc[r][3] = fmaf(av[r], b4.w, acc[r][3]);
            }
        }
        __syncthreads();
    }

    const float4 bsv = *(const float4*)(bias + n0 + cg);
#pragma unroll
    for (int r = 0; r < 8; r++) {
        const int row = m0 + rg + r;
        float4 o;
        o.x = acc[r][0] + bsv.x;
        o.y = acc[r][1] + bsv.y;
        o.z = acc[r][2] + bsv.z;
        o.w = acc[r][3] + bsv.w;
        *(float4*)&g_xW[dir][row][n0 + cg] = o;
    }
}

// ---------------- one LSTM timestep, both directions ------------------------
// CTA tile: 32 batch rows x 64 unit-cols x 4 gates (gate-aligned so the
// elementwise cell update can be fused). Grid (8 utiles, 8 mtiles, 2 dirs).
__device__ __forceinline__ float sigmoidf_(float v) { return 1.0f / (1.0f + expf(-v)); }

__global__ void __launch_bounds__(256)
step_kernel(const int* __restrict__ x,
            const float* __restrict__ Uf, const float* __restrict__ Ub, int t)
{
    const int ut  = blockIdx.x;          // 0..7
    const int mtb = blockIdx.y;          // 0..7
    const int dir = blockIdx.z;
    const float* __restrict__ U = dir ? Ub : Uf;
    const int u0  = ut * 64;
    const int m0  = mtb * 32;
    const int tt  = dir ? (T_LEN - 1 - t) : t;
    const int pin = t & 1, pout = pin ^ 1;

    __shared__ float sh[32][33];         // h tile transposed [k][m], conflict-free pad
    __shared__ float su[4][32][64];      // U tiles per gate [g][k][c]

    const int tid = threadIdx.x;
    const int r4  = (tid >> 5) * 4;      // 8 row-groups of 4 rows (uniform per warp)
    const int c2  = (tid & 31) * 2;      // 32 col-groups of 2 cols

    float acc[4][4][2];                  // [gate][row][col]
#pragma unroll
    for (int g = 0; g < 4; g++)
#pragma unroll
        for (int r = 0; r < 4; r++) { acc[g][r][0] = 0.0f; acc[g][r][1] = 0.0f; }

    const float* __restrict__ hin = &g_h[dir][pin][0][0];
    const int hr = tid >> 3;             // 0..31 (row within tile)
    const int hk = (tid & 7) * 4;        // k offset within chunk

    for (int k0 = 0; k0 < UNITS; k0 += 32) {
        // h tile: 32x32 floats, 1 float4 per thread, transposed conflict-free store
        {
            float4 hv = *(const float4*)(hin + (m0 + hr) * UNITS + k0 + hk);
            sh[hk + 0][hr] = hv.x;
            sh[hk + 1][hr] = hv.y;
            sh[hk + 2][hr] = hv.z;
            sh[hk + 3][hr] = hv.w;
        }
        // U tiles: 4 gates x 32k x 64c = 2048 float4, 8 per thread, contiguous smem
#pragma unroll
        for (int j = 0; j < 8; j++) {
            int idx = tid + j * 256;
            int g   = idx >> 9;
            int rem = idx & 511;
            int kk  = rem >> 4;
            int cc  = (rem & 15) * 4;
            *(float4*)&su[g][kk][cc] =
                *(const float4*)(U + (size_t)(k0 + kk) * GATEC + g * UNITS + u0 + cc);
        }
        __syncthreads();

#pragma unroll 8
        for (int k = 0; k < 32; k++) {
            const float a0 = sh[k][r4 + 0];
            const float a1 = sh[k][r4 + 1];
            const float a2 = sh[k][r4 + 2];
            const float a3 = sh[k][r4 + 3];
#pragma unroll
            for (int g = 0; g < 4; g++) {
                const float2 b = *(const float2*)&su[g][k][c2];
                acc[g][0][0] = fmaf(a0, b.x, acc[g][0][0]);
                acc[g][0][1] = fmaf(a0, b.y, acc[g][0][1]);
                acc[g][1][0] = fmaf(a1, b.x, acc[g][1][0]);
                acc[g][1][1] = fmaf(a1, b.y, acc[g][1][1]);
                acc[g][2][0] = fmaf(a2, b.x, acc[g][2][0]);
                acc[g][2][1] = fmaf(a2, b.y, acc[g][2][1]);
                acc[g][3][0] = fmaf(a3, b.x, acc[g][3][0]);
                acc[g][3][1] = fmaf(a3, b.y, acc[g][3][1]);
            }
        }
        __syncthreads();
    }

    // fused gate math + masked state update (Keras semantics: hold when masked)
#pragma unroll
    for (int r = 0; r < 4; r++) {
        const int n   = m0 + r4 + r;
        const int row = n * T_LEN + tt;
        const bool msk = (x[row] != 0);
        const float* xw = &g_xW[dir][row][u0 + c2];
        float2 zi = *(const float2*)(xw + 0 * UNITS);
        float2 zf = *(const float2*)(xw + 1 * UNITS);
        float2 zg = *(const float2*)(xw + 2 * UNITS);
        float2 zo = *(const float2*)(xw + 3 * UNITS);
        zi.x += acc[0][r][0]; zi.y += acc[0][r][1];
        zf.x += acc[1][r][0]; zf.y += acc[1][r][1];
        zg.x += acc[2][r][0]; zg.y += acc[2][r][1];
        zo.x += acc[3][r][0]; zo.y += acc[3][r][1];

        const float2 cold = *(const float2*)&g_c[dir][n][u0 + c2];
        const float2 hold = *(const float2*)&g_h[dir][pin][n][u0 + c2];

        float2 cn, hn;
        {
            float ig = sigmoidf_(zi.x), fg = sigmoidf_(zf.x);
            float gg = tanhf(zg.x),     og = sigmoidf_(zo.x);
            cn.x = fmaf(fg, cold.x, ig * gg);
            hn.x = og * tanhf(cn.x);
        }
        {
            float ig = sigmoidf_(zi.y), fg = sigmoidf_(zf.y);
            float gg = tanhf(zg.y),     og = sigmoidf_(zo.y);
            cn.y = fmaf(fg, cold.y, ig * gg);
            hn.y = og * tanhf(cn.y);
        }
        if (!msk) { cn = cold; hn = hold; }
        *(float2*)&g_c[dir][n][u0 + c2]        = cn;
        *(float2*)&g_h[dir][pout][n][u0 + c2]  = hn;
    }
}

// ---------------- write output: concat(h_fwd, h_bwd) ------------------------
__global__ void out_kernel(float* __restrict__ out)
{
    int i = blockIdx.x * 256 + threadIdx.x;   // over N_SEQ*UNITS
    if (i < N_SEQ * UNITS) {
        int n = i >> 9;
        int u = i & 511;
        // after T_LEN=128 steps, final state lives in parity (T_LEN & 1) == 0
        out[n * 1024 + u]       = g_h[0][0][n][u];
        out[n * 1024 + 512 + u] = g_h[1][0][n][u];
    }
}

// ---------------- launch ----------------------------------------------------
extern "C" void kernel_launch(void* const* d_in, const int* in_sizes, int n_in,
                              void* d_out, int out_size)
{
    const int*   x   = (const int*)  d_in[0];
    const float* emb = (const float*)d_in[1];
    const float* Wf  = (const float*)d_in[2];
    const float* Uf  = (const float*)d_in[3];
    const float* bf  = (const float*)d_in[4];
    const float* Wb  = (const float*)d_in[5];
    const float* Ub  = (const float*)d_in[6];
    const float* bb  = (const float*)d_in[7];
    float* out = (float*)d_out;
    (void)in_sizes; (void)n_in; (void)out_size;

    init_kernel<<<3072, 256>>>();

    dim3 gx(32, 256, 2);
    xw_kernel<<<gx, 256>>>(x, emb, Wf, bf, Wb, bb);

    dim3 gs(8, 8, 2);
    for (int t = 0; t < T_LEN; t++)
        step_kernel<<<gs, 256>>>(x, Uf, Ub, t);

    out_kernel<<<512, 256>>>(out);
}

// round 4
// speedup vs baseline: 1.0328x; 1.0328x over previous
#include <cuda_runtime.h>
#include <math.h>

#define N_SEQ   256
#define T_LEN   128
#define EMBED   512
#define UNITS   512
#define GATEC   2048          // 4*UNITS
#define M_ALL   (N_SEQ * T_LEN)   // 32768

typedef unsigned long long ull;

// ---------------- packed f32x2 helpers (sm_103a FFMA2 path) -----------------
__device__ __forceinline__ ull pk2(float x, float y) {
    ull r; asm("mov.b64 %0, {%1,%2};" : "=l"(r) : "f"(x), "f"(y)); return r;
}
__device__ __forceinline__ void upk2(ull v, float& lo, float& hi) {
    asm("mov.b64 {%0,%1}, %2;" : "=f"(lo), "=f"(hi) : "l"(v));
}
__device__ __forceinline__ void ffma2(ull& d, ull a, ull b) {
    asm("fma.rn.f32x2 %0, %1, %2, %0;" : "+l"(d) : "l"(a), "l"(b));
}

// ---------------- scratch (static device globals; no allocation allowed) ----
__device__ float g_xW[2][M_ALL][GATEC];        // precomputed x@W + b, per direction
__device__ float g_h[2][2][N_SEQ][UNITS];      // [dir][parity][n][u] double-buffered hidden
__device__ float g_c[2][N_SEQ][UNITS];         // [dir][n][u] cell state

// ---------------- init: zero recurrent state every call (graph replays!) ----
__global__ void init_kernel()
{
    int i = blockIdx.x * 256 + threadIdx.x;
    float* h = &g_h[0][0][0][0];
    float* c = &g_c[0][0][0];
    if (i < 2 * 2 * N_SEQ * UNITS) h[i] = 0.0f;
    if (i < 2 * N_SEQ * UNITS)     c[i] = 0.0f;
}

// ---------------- fused embedding gather + input projection GEMM ------------
// out[dir][m][n] = emb_table[ids[m]] @ W_dir + b_dir
// CTA tile: 128 (M) x 64 (N), 256 threads, 8x4 micro-tile, f32x2 row-paired.
__global__ void __launch_bounds__(256, 2)
xw_kernel(const int* __restrict__ x, const float* __restrict__ emb,
          const float* __restrict__ Wf, const float* __restrict__ bf,
          const float* __restrict__ Wb, const float* __restrict__ bb)
{
    const int nt  = blockIdx.x;          // 0..31  (N tiles of 64)
    const int mt  = blockIdx.y;          // 0..255 (M tiles of 128)
    const int dir = blockIdx.z;          // 0 fwd, 1 bwd
    const float* __restrict__ W    = dir ? Wb : Wf;
    const float* __restrict__ bias = dir ? bb : bf;
    const int m0 = mt * 128;
    const int n0 = nt * 64;

    __shared__ __align__(16) float sa[32][132];  // A tile, transposed [k][m]
    __shared__ __align__(16) float sb[32][64];   // B tile [k][n]
    __shared__ int   sid[128];

    const int tid = threadIdx.x;
    if (tid < 128) sid[tid] = x[m0 + tid];
    __syncthreads();

    // A-load mapping: each thread loads 16 floats (4x float4) of one emb row
    const int arow = tid & 127;
    const int aseg = (tid >> 7) * 16;
    const size_t aoff = (size_t)sid[arow] * EMBED + aseg;

    // compute mapping: 16x16 thread grid, 8 rows (4 pairs) x 4 cols per thread
    const int rg = (tid >> 4) * 8;
    const int cg = (tid & 15) * 4;

    ull acc[4][4];                        // [row-pair][col]
#pragma unroll
    for (int p = 0; p < 4; p++)
#pragma unroll
        for (int c = 0; c < 4; c++) acc[p][c] = 0ull;

    for (int k0 = 0; k0 < EMBED; k0 += 32) {
        // gather A (emb rows) -> transposed smem
#pragma unroll
        for (int i = 0; i < 4; i++) {
            float4 v = *(const float4*)(emb + aoff + k0 + i * 4);
            int kk = aseg + i * 4;
            sa[kk + 0][arow] = v.x;
            sa[kk + 1][arow] = v.y;
            sa[kk + 2][arow] = v.z;
            sa[kk + 3][arow] = v.w;
        }
        // load B: 32x64 floats = 512 float4, 2 per thread
#pragma unroll
        for (int j = 0; j < 2; j++) {
            int idx = tid * 2 + j;
            int kk  = idx >> 4;
            int cc  = (idx & 15) * 4;
            *(float4*)&sb[kk][cc] =
                *(const float4*)(W + (size_t)(k0 + kk) * GATEC + n0 + cc);
        }
        __syncthreads();

#pragma unroll 8
        for (int k = 0; k < 32; k++) {
            const float4 b4 = *(const float4*)&sb[k][cg];
            const ull bx = pk2(b4.x, b4.x);
            const ull by = pk2(b4.y, b4.y);
            const ull bz = pk2(b4.z, b4.z);
            const ull bw = pk2(b4.w, b4.w);
#pragma unroll
            for (int p = 0; p < 4; p++) {
                const ull a = *(const ull*)&sa[k][rg + 2 * p];  // two rows
                ffma2(acc[p][0], a, bx);
                ffma2(acc[p][1], a, by);
                ffma2(acc[p][2], a, bz);
                ffma2(acc[p][3], a, bw);
            }
        }
        __syncthreads();
    }

    const float4 bsv = *(const float4*)(bias + n0 + cg);
#pragma unroll
    for (int p = 0; p < 4; p++) {
        float lo[4], hi[4];
#pragma unroll
        for (int c = 0; c < 4; c++) upk2(acc[p][c], lo[c], hi[c]);
        const int row0 = m0 + rg + 2 * p;
        float4 o0, o1;
        o0.x = lo[0] + bsv.x; o0.y = lo[1] + bsv.y;
        o0.z = lo[2] + bsv.z; o0.w = lo[3] + bsv.w;
        o1.x = hi[0] + bsv.x; o1.y = hi[1] + bsv.y;
        o1.z = hi[2] + bsv.z; o1.w = hi[3] + bsv.w;
        *(float4*)&g_xW[dir][row0][n0 + cg]     = o0;
        *(float4*)&g_xW[dir][row0 + 1][n0 + cg] = o1;
    }
}

// ---------------- one LSTM timestep, both directions ------------------------
// CTA tile: 32 batch rows x 32 unit-cols x 4 gates. 128 threads; thread tile
// = 8 rows (4 f32x2 pairs) x 1 col x 4 gates -> gates thread-local so the
// masked cell update stays fused. Grid (16 utiles, 8 mtiles, 2 dirs) = 256.
__device__ __forceinline__ float sigmoidf_(float v) { return 1.0f / (1.0f + expf(-v)); }

__global__ void __launch_bounds__(128, 2)
step_kernel(const int* __restrict__ x,
            const float* __restrict__ Uf, const float* __restrict__ Ub, int t)
{
    const int ut  = blockIdx.x;          // 0..15
    const int mtb = blockIdx.y;          // 0..7
    const int dir = blockIdx.z;
    const float* __restrict__ U = dir ? Ub : Uf;
    const int u0  = ut * 32;
    const int m0  = mtb * 32;
    const int tt  = dir ? (T_LEN - 1 - t) : t;
    const int pin = t & 1, pout = pin ^ 1;

    __shared__ __align__(16) float sh[32][34];     // h tile transposed [k][m]
    __shared__ __align__(16) float su[4][32][32];  // U tiles per gate [g][k][c]

    const int tid = threadIdx.x;
    const int rw  = tid >> 5;            // warp id 0..3 -> row group
    const int r0  = rw * 8;              // 8 rows = 4 pairs (uniform per warp)
    const int cl  = tid & 31;            // 1 col per thread, conflict-free

    ull acc[4][4];                       // [gate][row-pair]
#pragma unroll
    for (int g = 0; g < 4; g++)
#pragma unroll
        for (int p = 0; p < 4; p++) acc[g][p] = 0ull;

    const float* __restrict__ hin = &g_h[dir][pin][0][0];

    for (int k0 = 0; k0 < UNITS; k0 += 32) {
        // h tile: 32x32 floats = 256 float4, 2 per thread, transposed store
#pragma unroll
        for (int j = 0; j < 2; j++) {
            int idx = tid * 2 + j;
            int hr  = idx >> 3;
            int hk  = (idx & 7) * 4;
            float4 hv = *(const float4*)(hin + (m0 + hr) * UNITS + k0 + hk);
            sh[hk + 0][hr] = hv.x;
            sh[hk + 1][hr] = hv.y;
            sh[hk + 2][hr] = hv.z;
            sh[hk + 3][hr] = hv.w;
        }
        // U tiles: 4 gates x 32k x 32c = 1024 float4, 8 per thread
#pragma unroll
        for (int j = 0; j < 8; j++) {
            int idx = tid + j * 128;
            int g   = idx >> 8;
            int rem = idx & 255;
            int kk  = rem >> 3;
            int cc  = (rem & 7) * 4;
            *(float4*)&su[g][kk][cc] =
                *(const float4*)(U + (size_t)(k0 + kk) * GATEC + g * UNITS + u0 + cc);
        }
        __syncthreads();

#pragma unroll 8
        for (int k = 0; k < 32; k++) {
            const ull a0 = *(const ull*)&sh[k][r0 + 0];   // broadcast row-pairs
            const ull a1 = *(const ull*)&sh[k][r0 + 2];
            const ull a2 = *(const ull*)&sh[k][r0 + 4];
            const ull a3 = *(const ull*)&sh[k][r0 + 6];
#pragma unroll
            for (int g = 0; g < 4; g++) {
                const float b = su[g][k][cl];
                const ull b2 = pk2(b, b);
                ffma2(acc[g][0], a0, b2);
                ffma2(acc[g][1], a1, b2);
                ffma2(acc[g][2], a2, b2);
                ffma2(acc[g][3], a3, b2);
            }
        }
        __syncthreads();
    }

    // fused gate math + masked state update (Keras semantics: hold when masked)
    const int uc = u0 + cl;
#pragma unroll
    for (int p = 0; p < 4; p++) {
        float zlo[4], zhi[4];
#pragma unroll
        for (int g = 0; g < 4; g++) upk2(acc[g][p], zlo[g], zhi[g]);
#pragma unroll
        for (int i = 0; i < 2; i++) {
            const int n   = m0 + r0 + 2 * p + i;
            const int row = n * T_LEN + tt;
            const bool msk = (x[row] != 0);
            const float* xw = &g_xW[dir][row][uc];
            float zi = xw[0 * UNITS] + (i ? zhi[0] : zlo[0]);
            float zf = xw[1 * UNITS] + (i ? zhi[1] : zlo[1]);
            float zg = xw[2 * UNITS] + (i ? zhi[2] : zlo[2]);
            float zo = xw[3 * UNITS] + (i ? zhi[3] : zlo[3]);

            const float cold = g_c[dir][n][uc];
            const float hold = g_h[dir][pin][n][uc];

            float ig = sigmoidf_(zi), fg = sigmoidf_(zf);
            float gg = tanhf(zg),     og = sigmoidf_(zo);
            float cn = fmaf(fg, cold, ig * gg);
            float hn = og * tanhf(cn);
            if (!msk) { cn = cold; hn = hold; }
            g_c[dir][n][uc]        = cn;
            g_h[dir][pout][n][uc]  = hn;
        }
    }
}

// ---------------- write output: concat(h_fwd, h_bwd) ------------------------
__global__ void out_kernel(float* __restrict__ out)
{
    int i = blockIdx.x * 256 + threadIdx.x;   // over N_SEQ*UNITS
    if (i < N_SEQ * UNITS) {
        int n = i >> 9;
        int u = i & 511;
        // after T_LEN=128 steps, final state lives in parity (T_LEN & 1) == 0
        out[n * 1024 + u]       = g_h[0][0][n][u];
        out[n * 1024 + 512 + u] = g_h[1][0][n][u];
    }
}

// ---------------- launch ----------------------------------------------------
extern "C" void kernel_launch(void* const* d_in, const int* in_sizes, int n_in,
                              void* d_out, int out_size)
{
    const int*   x   = (const int*)  d_in[0];
    const float* emb = (const float*)d_in[1];
    const float* Wf  = (const float*)d_in[2];
    const float* Uf  = (const float*)d_in[3];
    const float* bf  = (const float*)d_in[4];
    const float* Wb  = (const float*)d_in[5];
    const float* Ub  = (const float*)d_in[6];
    const float* bb  = (const float*)d_in[7];
    float* out = (float*)d_out;
    (void)in_sizes; (void)n_in; (void)out_size;

    init_kernel<<<3072, 256>>>();

    dim3 gx(32, 256, 2);
    xw_kernel<<<gx, 256>>>(x, emb, Wf, bf, Wb, bb);

    dim3 gs(16, 8, 2);
    for (int t = 0; t < T_LEN; t++)
        step_kernel<<<gs, 128>>>(x, Uf, Ub, t);

    out_kernel<<<512, 256>>>(out);
}